// round 13
// baseline (speedup 1.0000x reference)
#include <cuda_runtime.h>

#define DIM  160
#define RP   164   // padded smem row (floats)
#define NB   2

// scale0: k=10 s=2 O=71 | scale1: k=20 s=5 O=25 | scale2: k=40 s=10 O=9
#define O0 71
#define O1 25
#define O2 9
#define NZ0 80
#define NZ1c 160
#define NZ2 80

// bufB: fields innermost, padded to 8 floats (32B) per output voxel.
#define PAD 8
#define R0SZ (NB*NZ0*O0*O0)     // 806,560 voxels
#define R1SZ (NB*NZ1c*O1*O1)    // 200,000
#define R2SZ (NB*NZ2*O2*O2)     //  12,960
#define OFF0 0
#define OFF1 (R0SZ*PAD)
#define OFF2 (OFF1 + R1SZ*PAD)

#define N3_0 (NB*O0*O0*O0)
#define N3_1 (NB*O1*O1*O1)
#define N3_2 (NB*O2*O2*O2)

#define NSTRIP0 24
#define STRIP0  3
#define NT0S   (NB*NSTRIP0*O0*O0)          // 241,968
#define NBLK0S ((NT0S + 255) / 256)        // 946
#define NBLK1  ((N3_1 + 255) / 256)        // 123
#define NBLK2  ((N3_2 + 255) / 256)        //   6
#define TOTBLK (NBLK0S + NBLK1 + NBLK2)

#define PB0 0
#define PB1 960
#define PB2 1088

__device__ float g_bufB[OFF2 + R2SZ*PAD];  // ~32.6 MB
__device__ float g_partials[1280];
__device__ unsigned int g_count = 0;

#define RAWF (2*16*RP)    // 16 rows x 2 vols = 5248 floats

// fused grid: sc1 (full z, 1 block per (b,z0)) then sc02 (CH0=36, 2 chunks)
#define G1  (NB*DIM)       // 320
#define G02 (NB*NZ0*2)     // 320
#define GALL (G1 + G02)
#define CH0 36

// sc1 smem: zwin 160*5*25 = 20000 + raw 5248 = 25248 floats = 100,992 B (max)
// sc02: 80*5*36 + 80*5*9 + 5248 = 23248 floats
#define SMEM_ALL ((NZ1c*5*O1 + RAWF) * (int)sizeof(float))

// ---------------------------------------------------------------------------
__device__ __forceinline__ void ldrow(const float* __restrict__ p, int lane,
                                      float4& r0, float4& r1) {
    const float4* q = (const float4*)p;
    r0 = q[lane];
    if (lane < 8) r1 = q[32 + lane];
}
__device__ __forceinline__ void strow(float* d, int lane,
                                      const float4& r0, const float4& r1) {
    float4* q = (float4*)d;
    q[lane] = r0;
    if (lane < 8) q[32 + lane] = r1;
}

template<int K>
__device__ __forceinline__ void win5(const float* xr, const float* yr, int z2s,
                                     float* out, int stride) {
    float a0 = 0.f, a1 = 0.f, a2 = 0.f, a3 = 0.f, a4 = 0.f;
#pragma unroll
    for (int t = 0; t < K; t++) {
        float xv = xr[z2s + 2 * t];
        float yv = yr[z2s + 2 * t];
        a0 += xv; a1 += yv; a2 += xv * xv; a3 += yv * yv; a4 += xv * yv;
    }
    out[0 * stride] = a0;
    out[1 * stride] = a1;
    out[2 * stride] = a2;
    out[3 * stride] = a3;
    out[4 * stride] = a4;
}

// write 5 field sums as one 32B-aligned packet (float4 + scalar)
__device__ __forceinline__ void st5(float* p, float a0, float a1, float a2,
                                    float a3, float a4) {
    *(float4*)p = make_float4(a0, a1, a2, a3);
    p[4] = a4;
}
// read 5 field sums
__device__ __forceinline__ void ld5(const float* __restrict__ p, float* a) {
    float4 q = *(const float4*)p;
    a[0] = q.x; a[1] = q.y; a[2] = q.z; a[3] = q.w;
    a[4] = p[4];
}

// ---------------------------------------------------------------------------
// sc1 body: one block per (b,z0), 512 threads, 10 batches of 16 rows,
// register double-buffer. zwin[160][5][25]; phase2 taps = planes 5*o1 + 2t.
// ---------------------------------------------------------------------------
__device__ __forceinline__ void body_sc1(int bid, const float* __restrict__ x,
                                         const float* __restrict__ y, float* sm) {
    const int O = O1, NZ = NZ1c;
    float* zwin = sm;                    // [NZ][5][O] = 20000
    float* raw  = sm + NZ * 5 * O;       // 16B-aligned (80000B)

    int z0 = bid % DIM;
    int b  = bid / DIM;
    int w    = threadIdx.x >> 5;
    int lane = threadIdx.x & 31;
    const float* xbase = x + (size_t)(b * DIM + z0) * DIM * DIM;
    const float* ybase = y + (size_t)(b * DIM + z0) * DIM * DIM;

    float4 fx0, fx1, fy0, fy1;
    ldrow(xbase + (size_t)w * DIM, lane, fx0, fx1);
    ldrow(ybase + (size_t)w * DIM, lane, fy0, fy1);

    for (int ib = 0; ib < 10; ib++) {
        __syncthreads();
        strow(raw + w * RP,        lane, fx0, fx1);
        strow(raw + (16 + w) * RP, lane, fy0, fy1);
        if (ib < 9) {
            int z1 = (ib + 1) * 16 + w;
            ldrow(xbase + (size_t)z1 * DIM, lane, fx0, fx1);
            ldrow(ybase + (size_t)z1 * DIM, lane, fy0, fy1);
        }
        __syncthreads();
        if (threadIdx.x < 16 * O) {
            int rl = threadIdx.x / O;
            int o2 = threadIdx.x % O;
            win5<20>(raw + rl * RP, raw + (16 + rl) * RP, 5 * o2,
                     zwin + (size_t)(ib * 16 + rl) * 125 + o2, O);
        }
    }
    __syncthreads();

    // phase2: one thread per (o1,o2), all 5 fields, 32B packet write
    for (int item = threadIdx.x; item < O * O; item += 512) {
        int o1 = item / O;
        int o2 = item % O;
        float a0 = 0.f, a1 = 0.f, a2 = 0.f, a3 = 0.f, a4 = 0.f;
#pragma unroll
        for (int t = 0; t < 20; t++) {
            const float* z = zwin + (size_t)(5 * o1 + 2 * t) * 125 + o2;
            a0 += z[0 * O]; a1 += z[1 * O]; a2 += z[2 * O];
            a3 += z[3 * O]; a4 += z[4 * O];
        }
        st5(g_bufB + OFF1 + (size_t)((((b * NZ) + z0) * O + o1) * O + o2) * PAD,
            a0, a1, a2, a3, a4);
    }
}

// ---------------------------------------------------------------------------
// sc02 body: even planes (z = 2*zi), CH0=36, 2 chunks; zwin2 in chunk 0.
// ---------------------------------------------------------------------------
__device__ __forceinline__ void body_sc02(int bid, const float* __restrict__ x,
                                          const float* __restrict__ y, float* sm) {
    const int NZ = 80;
    float* zwin0 = sm;                          // [80][5][CH0] = 14400
    float* zwin2 = sm + NZ * 5 * CH0;           // [80][5][9]   = 3600
    float* raw   = zwin2 + NZ * 5 * O2;         // 18000 floats (72000B, aligned)

    int ch  = bid & 1;  bid >>= 1;
    int z0i = bid % NZ;
    int b   = bid / NZ;
    int z0  = 2 * z0i;
    int obase = ch * CH0;
    int w    = threadIdx.x >> 5;
    int lane = threadIdx.x & 31;
    const float* xbase = x + (size_t)(b * DIM + z0) * DIM * DIM;
    const float* ybase = y + (size_t)(b * DIM + z0) * DIM * DIM;

    float4 fx0, fx1, fy0, fy1;
    ldrow(xbase + (size_t)(2 * w) * DIM, lane, fx0, fx1);
    ldrow(ybase + (size_t)(2 * w) * DIM, lane, fy0, fy1);

    for (int ib = 0; ib < 5; ib++) {
        int rb = ib * 16;
        __syncthreads();
        strow(raw + w * RP,        lane, fx0, fx1);
        strow(raw + (16 + w) * RP, lane, fy0, fy1);
        if (ib < 4) {
            int z1 = 2 * (rb + 16 + w);
            ldrow(xbase + (size_t)z1 * DIM, lane, fx0, fx1);
            ldrow(ybase + (size_t)z1 * DIM, lane, fy0, fy1);
        }
        __syncthreads();

        int nit = (ch == 0) ? (16 * CH0 + 16 * O2) : (16 * CH0);
        for (int it = threadIdx.x; it < nit; it += 512) {
            if (it < 16 * CH0) {
                int rl  = it / CH0;
                int o2l = it % CH0;
                int o2  = obase + o2l;
                if (o2 < O0)
                    win5<10>(raw + rl * RP, raw + (16 + rl) * RP, 2 * o2,
                             zwin0 + (size_t)(rb + rl) * 5 * CH0 + o2l, CH0);
            } else {
                int it2 = it - 16 * CH0;
                int rl = it2 / O2;
                int o2 = it2 % O2;
                win5<40>(raw + rl * RP, raw + (16 + rl) * RP, 10 * o2,
                         zwin2 + (size_t)(rb + rl) * 5 * O2 + o2, O2);
            }
        }
    }
    __syncthreads();

    // phase2 sc0: thread per (o1, o2l), 10 consecutive compact planes
    for (int item = threadIdx.x; item < O0 * CH0; item += 512) {
        int o1  = item / CH0;
        int o2l = item % CH0;
        int o2  = obase + o2l;
        if (o2 >= O0) continue;
        float a0 = 0.f, a1 = 0.f, a2 = 0.f, a3 = 0.f, a4 = 0.f;
#pragma unroll
        for (int t = 0; t < 10; t++) {
            const float* z = zwin0 + (size_t)(o1 + t) * 5 * CH0 + o2l;
            a0 += z[0 * CH0]; a1 += z[1 * CH0]; a2 += z[2 * CH0];
            a3 += z[3 * CH0]; a4 += z[4 * CH0];
        }
        st5(g_bufB + OFF0 + (size_t)((((b * NZ) + z0i) * O0 + o1) * O0 + o2) * PAD,
            a0, a1, a2, a3, a4);
    }
    // phase2 sc2 (chunk 0): thread per (o1,o2), planes 5*o1 + t, t<40
    if (ch == 0) {
        for (int item = threadIdx.x; item < O2 * O2; item += 512) {
            int o1 = item / O2;
            int o2 = item % O2;
            float a0 = 0.f, a1 = 0.f, a2 = 0.f, a3 = 0.f, a4 = 0.f;
#pragma unroll
            for (int t = 0; t < 40; t++) {
                const float* z = zwin2 + (size_t)(5 * o1 + t) * 5 * O2 + o2;
                a0 += z[0 * O2]; a1 += z[1 * O2]; a2 += z[2 * O2];
                a3 += z[3 * O2]; a4 += z[4 * O2];
            }
            st5(g_bufB + OFF2 + (size_t)((((b * NZ) + z0i) * O2 + o1) * O2 + o2) * PAD,
                a0, a1, a2, a3, a4);
        }
    }
}

__global__ __launch_bounds__(512) void fused_all(const float* __restrict__ x,
                                                 const float* __restrict__ y) {
    extern __shared__ float sm[];
    int b = blockIdx.x;
    if (b < G1) body_sc1(b, x, y, sm);
    else        body_sc02(b - G1, x, y, sm);
}

// ---------------------------------------------------------------------------
// pass34 + fused finalize (interleaved bufB: 2 loads per plane)
// ---------------------------------------------------------------------------
__device__ __forceinline__ float lncc_eval(float s0, float s1, float s2,
                                           float s3, float s4, float numel) {
    float xm = s0 / numel;
    float ym = s1 / numel;
    float cross = s4 - ym * s0 - xm * s1 + ym * xm * numel;
    float xvar  = s2 - 2.f * xm * s0 + xm * xm * numel;
    float yvar  = s3 - 2.f * ym * s1 + ym * ym * numel;
    return cross * cross / (xvar * yvar + 1e-5f);
}

template<int K, int O, int NZ, int B0, int TS, int OFF, int N3>
__device__ __forceinline__ float pass34_gather(int blk) {
    const float numel = (float)K * (float)K * (float)K;
    int idx = blk * 256 + threadIdx.x;
    if (idx >= N3) return 0.f;
    int o2 = idx % O;
    int r  = idx / O;
    int o1 = r % O;  r /= O;
    int o0 = r % O;
    int b  = r / O;
    const float* p = g_bufB + OFF +
        (size_t)(((b * NZ + B0 * o0) * O + o1) * O + o2) * PAD;
    const int tapstride = TS * O * O * PAD;
    float acc[5] = {0.f, 0.f, 0.f, 0.f, 0.f};
#pragma unroll
    for (int t = 0; t < K; t++) {
        float a[5];
        ld5(p + (size_t)t * tapstride, a);
#pragma unroll
        for (int f = 0; f < 5; f++) acc[f] += a[f];
    }
    return lncc_eval(acc[0], acc[1], acc[2], acc[3], acc[4], numel);
}

template<int NW>
__device__ __forceinline__ float strip0_fixed(const float* __restrict__ p0,
                                              int o0s) {
    const int PS = O0 * O0 * PAD;
    float a[5] = {0.f, 0.f, 0.f, 0.f, 0.f};
#pragma unroll
    for (int j = 0; j < 9; j++) {
        float v[5];
        ld5(p0 + (size_t)(o0s + j) * PS, v);
#pragma unroll
        for (int f = 0; f < 5; f++) a[f] += v[f];
    }
    float vsum = 0.f;
#pragma unroll
    for (int s = 0; s < NW; s++) {
        float v[5];
        ld5(p0 + (size_t)(o0s + 9 + s) * PS, v);
#pragma unroll
        for (int f = 0; f < 5; f++) a[f] += v[f];
        vsum += lncc_eval(a[0], a[1], a[2], a[3], a[4], 1000.0f);
        ld5(p0 + (size_t)(o0s + s) * PS, v);
#pragma unroll
        for (int f = 0; f < 5; f++) a[f] -= v[f];
    }
    return vsum;
}

__device__ __forceinline__ float pass34_strip0(int blk) {
    int idx = blk * 256 + threadIdx.x;
    if (idx >= NT0S) return 0.f;
    int o2 = idx % O0;
    int r  = idx / O0;
    int o1 = r % O0;  r /= O0;
    int strip = r % NSTRIP0;
    int b     = r / NSTRIP0;
    int o0s = strip * STRIP0;
    const float* p0 = g_bufB + OFF0 +
        (size_t)(((b * NZ0) * O0 + o1) * O0 + o2) * PAD;
    if (o0s + STRIP0 <= O0) return strip0_fixed<3>(p0, o0s);
    return strip0_fixed<2>(p0, o0s);
}

__global__ __launch_bounds__(256) void pass34_all(float* __restrict__ out) {
    int bb = blockIdx.x;
    float v;
    int pslot;
    if (bb < NBLK0S) {
        v = pass34_strip0(bb);
        pslot = PB0 + bb;
    } else if (bb < NBLK0S + NBLK1) {
        v = pass34_gather<20, O1, NZ1c, 5, 2, OFF1, N3_1>(bb - NBLK0S);
        pslot = PB1 + (bb - NBLK0S);
    } else {
        v = pass34_gather<40, O2, NZ2, 5, 1, OFF2, N3_2>(bb - NBLK0S - NBLK1);
        pslot = PB2 + (bb - NBLK0S - NBLK1);
    }

    __shared__ float wsum[8];
    int lane = threadIdx.x & 31;
    int wid  = threadIdx.x >> 5;
#pragma unroll
    for (int o = 16; o > 0; o >>= 1) v += __shfl_down_sync(0xffffffffu, v, o);
    if (lane == 0) wsum[wid] = v;
    __syncthreads();
    if (wid == 0) {
        v = (lane < 8) ? wsum[lane] : 0.f;
#pragma unroll
        for (int o = 4; o > 0; o >>= 1) v += __shfl_down_sync(0xffffffffu, v, o);
        if (lane == 0) g_partials[pslot] = v;
    }

    __shared__ bool isLast;
    __threadfence();
    if (threadIdx.x == 0) {
        unsigned int old = atomicAdd(&g_count, 1u);
        isLast = (old == TOTBLK - 1);
    }
    __syncthreads();
    if (!isLast) return;
    __threadfence();

    __shared__ float sh[256];
    const int   pbase[3] = {PB0, PB1, PB2};
    const int   nblk[3]  = {NBLK0S, NBLK1, NBLK2};
    const float ninv[3]  = {1.0f / N3_0, 1.0f / N3_1, 1.0f / N3_2};
    const float wsc[3]   = {0.1f, 0.3f, 0.6f};
    float total = 0.f;
    for (int sc = 0; sc < 3; sc++) {
        float a = 0.f;
        for (int i = threadIdx.x; i < nblk[sc]; i += 256) a += g_partials[pbase[sc] + i];
        sh[threadIdx.x] = a;
        __syncthreads();
#pragma unroll
        for (int st = 128; st > 0; st >>= 1) {
            if (threadIdx.x < st) sh[threadIdx.x] += sh[threadIdx.x + st];
            __syncthreads();
        }
        if (threadIdx.x == 0) total += (1.0f - sh[0] * ninv[sc]) * wsc[sc];
        __syncthreads();
    }
    if (threadIdx.x == 0) {
        out[0] = total;
        g_count = 0;
    }
}

extern "C" void kernel_launch(void* const* d_in, const int* in_sizes, int n_in,
                              void* d_out, int out_size) {
    const float* x = (const float*)d_in[0];
    const float* y = (const float*)d_in[1];
    float* out = (float*)d_out;

    cudaFuncSetAttribute(fused_all,
                         cudaFuncAttributeMaxDynamicSharedMemorySize, SMEM_ALL);

    fused_all<<<GALL, 512, SMEM_ALL>>>(x, y);
    pass34_all<<<TOTBLK, 256>>>(out);
}

// round 14
// speedup vs baseline: 1.1356x; 1.1356x over previous
#include <cuda_runtime.h>

#define DIM  160
#define RP   164   // padded smem row (floats)
#define NB   2

// scale0: k=10 s=2 O=71 | scale1: k=20 s=5 O=25 | scale2: k=40 s=10 O=9
#define O0 71
#define O0W 72     // padded o2 row stride for sc0 (16B-alignable)
#define O1 25
#define O2 9
#define NZ0 80
#define NZ1c 160
#define NZ2 80

// bufB: planar fields. sc0 rows padded to O0W.
#define FS0P (NB*NZ0*O0*O0W)    // 817,920 per field
#define FS1 (NB*NZ1c*O1*O1)     // 200,000
#define FS2 (NB*NZ2*O2*O2)      //  12,960
#define OFF0 0
#define OFF1 (5*FS0P)
#define OFF2 (OFF1 + 5*FS1)

#define N3_0 (NB*O0*O0*O0)
#define N3_1 (NB*O1*O1*O1)
#define N3_2 (NB*O2*O2*O2)

// pass34: sc0 vectorized strips — thread = (b, strip, o1, o2 group of 4)
#define NSTRIP0 24
#define STRIP0  3
#define NG0     18                          // ceil(71/4)
#define NT0V   (NB*NSTRIP0*O0*NG0)          // 61,344
#define NBLK0V ((NT0V + 255) / 256)         // 240
#define NBLK1  ((N3_1 + 255) / 256)         // 123
#define NBLK2  ((N3_2 + 255) / 256)         //   6
#define TOTBLK (NBLK0V + NBLK1 + NBLK2)     // 369

#define PB0 0
#define PB1 256
#define PB2 384

__device__ float g_bufB[OFF2 + 5*FS2];  // ~20.9 MB
__device__ float g_partials[512];
__device__ unsigned int g_count = 0;

#define RAWF (2*16*RP)    // 16 rows x 2 vols = 5248 floats

// fused grid: sc1 (full z) then sc02 (CH0=36, 2 chunks)
#define G1  (NB*DIM)       // 320
#define G02 (NB*NZ0*2)     // 320
#define GALL (G1 + G02)
#define CH0 36

// sc1 smem: zwin 160*5*25 = 20000 + raw 5248 = 25248 floats = 100,992 B (max)
#define SMEM_ALL ((NZ1c*5*O1 + RAWF) * (int)sizeof(float))

// ---------------------------------------------------------------------------
__device__ __forceinline__ void ldrow(const float* __restrict__ p, int lane,
                                      float4& r0, float4& r1) {
    const float4* q = (const float4*)p;
    r0 = q[lane];
    if (lane < 8) r1 = q[32 + lane];
}
__device__ __forceinline__ void strow(float* d, int lane,
                                      const float4& r0, const float4& r1) {
    float4* q = (float4*)d;
    q[lane] = r0;
    if (lane < 8) q[32 + lane] = r1;
}

template<int K>
__device__ __forceinline__ void win5(const float* xr, const float* yr, int z2s,
                                     float* out, int stride) {
    float a0 = 0.f, a1 = 0.f, a2 = 0.f, a3 = 0.f, a4 = 0.f;
#pragma unroll
    for (int t = 0; t < K; t++) {
        float xv = xr[z2s + 2 * t];
        float yv = yr[z2s + 2 * t];
        a0 += xv; a1 += yv; a2 += xv * xv; a3 += yv * yv; a4 += xv * yv;
    }
    out[0 * stride] = a0;
    out[1 * stride] = a1;
    out[2 * stride] = a2;
    out[3 * stride] = a3;
    out[4 * stride] = a4;
}

// ---------------------------------------------------------------------------
// sc1 body (R9): one block per (b,z0), 512 threads, 10 batches of 16 rows,
// register double-buffer. zwin[160][5][25]; phase2 taps = planes 5*o1 + 2t.
// ---------------------------------------------------------------------------
__device__ __forceinline__ void body_sc1(int bid, const float* __restrict__ x,
                                         const float* __restrict__ y, float* sm) {
    const int O = O1, NZ = NZ1c;
    float* zwin = sm;                    // [NZ][5][O] = 20000
    float* raw  = sm + NZ * 5 * O;       // 80000 B -> 16B aligned

    int z0 = bid % DIM;
    int b  = bid / DIM;
    int w    = threadIdx.x >> 5;
    int lane = threadIdx.x & 31;
    const float* xbase = x + (size_t)(b * DIM + z0) * DIM * DIM;
    const float* ybase = y + (size_t)(b * DIM + z0) * DIM * DIM;

    float4 fx0, fx1, fy0, fy1;
    ldrow(xbase + (size_t)w * DIM, lane, fx0, fx1);
    ldrow(ybase + (size_t)w * DIM, lane, fy0, fy1);

    for (int ib = 0; ib < 10; ib++) {
        __syncthreads();
        strow(raw + w * RP,        lane, fx0, fx1);
        strow(raw + (16 + w) * RP, lane, fy0, fy1);
        if (ib < 9) {
            int z1 = (ib + 1) * 16 + w;
            ldrow(xbase + (size_t)z1 * DIM, lane, fx0, fx1);
            ldrow(ybase + (size_t)z1 * DIM, lane, fy0, fy1);
        }
        __syncthreads();
        if (threadIdx.x < 16 * O) {
            int rl = threadIdx.x / O;
            int o2 = threadIdx.x % O;
            win5<20>(raw + rl * RP, raw + (16 + rl) * RP, 5 * o2,
                     zwin + (size_t)(ib * 16 + rl) * 125 + o2, O);
        }
    }
    __syncthreads();

    const int ITEMS = 5 * O * O;
    for (int item = threadIdx.x; item < ITEMS; item += 512) {
        int f   = item / (O * O);
        int rem = item % (O * O);
        int o1  = rem / O;
        int o2  = rem % O;
        float acc = 0.f;
#pragma unroll
        for (int t = 0; t < 20; t++)
            acc += zwin[(size_t)(5 * o1 + 2 * t) * 125 + f * O + o2];
        g_bufB[OFF1 + f * FS1 + (((b * NZ) + z0) * O + o1) * O + o2] = acc;
    }
}

// ---------------------------------------------------------------------------
// sc02 body (R9): even planes (z = 2*zi), CH0=36, 2 chunks; zwin2 in chunk 0.
// sc0 output rows padded to O0W.
// ---------------------------------------------------------------------------
__device__ __forceinline__ void body_sc02(int bid, const float* __restrict__ x,
                                          const float* __restrict__ y, float* sm) {
    const int NZ = 80;
    float* zwin0 = sm;                          // [80][5][CH0] = 14400
    float* zwin2 = sm + NZ * 5 * CH0;           // [80][5][9]   = 3600
    float* raw   = zwin2 + NZ * 5 * O2;         // 18000 floats, 16B aligned

    int ch  = bid & 1;  bid >>= 1;
    int z0i = bid % NZ;
    int b   = bid / NZ;
    int z0  = 2 * z0i;
    int obase = ch * CH0;
    int w    = threadIdx.x >> 5;
    int lane = threadIdx.x & 31;
    const float* xbase = x + (size_t)(b * DIM + z0) * DIM * DIM;
    const float* ybase = y + (size_t)(b * DIM + z0) * DIM * DIM;

    float4 fx0, fx1, fy0, fy1;
    ldrow(xbase + (size_t)(2 * w) * DIM, lane, fx0, fx1);
    ldrow(ybase + (size_t)(2 * w) * DIM, lane, fy0, fy1);

    for (int ib = 0; ib < 5; ib++) {
        int rb = ib * 16;
        __syncthreads();
        strow(raw + w * RP,        lane, fx0, fx1);
        strow(raw + (16 + w) * RP, lane, fy0, fy1);
        if (ib < 4) {
            int z1 = 2 * (rb + 16 + w);
            ldrow(xbase + (size_t)z1 * DIM, lane, fx0, fx1);
            ldrow(ybase + (size_t)z1 * DIM, lane, fy0, fy1);
        }
        __syncthreads();

        int nit = (ch == 0) ? (16 * CH0 + 16 * O2) : (16 * CH0);
        for (int it = threadIdx.x; it < nit; it += 512) {
            if (it < 16 * CH0) {
                int rl  = it / CH0;
                int o2l = it % CH0;
                int o2  = obase + o2l;
                if (o2 < O0)
                    win5<10>(raw + rl * RP, raw + (16 + rl) * RP, 2 * o2,
                             zwin0 + (size_t)(rb + rl) * 5 * CH0 + o2l, CH0);
            } else {
                int it2 = it - 16 * CH0;
                int rl = it2 / O2;
                int o2 = it2 % O2;
                win5<40>(raw + rl * RP, raw + (16 + rl) * RP, 10 * o2,
                         zwin2 + (size_t)(rb + rl) * 5 * O2 + o2, O2);
            }
        }
    }
    __syncthreads();

    // phase2 sc0: taps = 10 consecutive compact planes; write padded rows
    {
        const int ITEMS = 5 * O0 * CH0;
        for (int item = threadIdx.x; item < ITEMS; item += 512) {
            int f   = item / (O0 * CH0);
            int rem = item % (O0 * CH0);
            int o1  = rem / CH0;
            int o2l = rem % CH0;
            int o2  = obase + o2l;
            if (o2 >= O0) continue;
            float acc = 0.f;
#pragma unroll
            for (int t = 0; t < 10; t++)
                acc += zwin0[(size_t)(o1 + t) * 5 * CH0 + f * CH0 + o2l];
            g_bufB[OFF0 + f * FS0P +
                   (size_t)(((b * NZ) + z0i) * O0 + o1) * O0W + o2] = acc;
        }
    }
    // phase2 sc2: taps = compact planes 5*o1 + t, t<40 (chunk 0 only)
    if (ch == 0) {
        const int ITEMS = 5 * O2 * O2;
        for (int item = threadIdx.x; item < ITEMS; item += 512) {
            int f   = item / (O2 * O2);
            int rem = item % (O2 * O2);
            int o1  = rem / O2;
            int o2  = rem % O2;
            float acc = 0.f;
#pragma unroll
            for (int t = 0; t < 40; t++)
                acc += zwin2[(size_t)(5 * o1 + t) * 5 * O2 + f * O2 + o2];
            g_bufB[OFF2 + f * FS2 + (((b * NZ) + z0i) * O2 + o1) * O2 + o2] = acc;
        }
    }
}

__global__ __launch_bounds__(512) void fused_all(const float* __restrict__ x,
                                                 const float* __restrict__ y) {
    extern __shared__ float sm[];
    int b = blockIdx.x;
    if (b < G1) body_sc1(b, x, y, sm);
    else        body_sc02(b - G1, x, y, sm);
}

// ---------------------------------------------------------------------------
// pass34 + fused finalize
// ---------------------------------------------------------------------------
__device__ __forceinline__ float lncc_eval(float s0, float s1, float s2,
                                           float s3, float s4, float numel) {
    float xm = s0 / numel;
    float ym = s1 / numel;
    float cross = s4 - ym * s0 - xm * s1 + ym * xm * numel;
    float xvar  = s2 - 2.f * xm * s0 + xm * xm * numel;
    float yvar  = s3 - 2.f * ym * s1 + ym * ym * numel;
    return cross * cross / (xvar * yvar + 1e-5f);
}

template<int K, int O, int NZ, int B0, int TS, int OFF, int FS, int N3>
__device__ __forceinline__ float pass34_gather(int blk) {
    const float numel = (float)K * (float)K * (float)K;
    int idx = blk * 256 + threadIdx.x;
    if (idx >= N3) return 0.f;
    int o2 = idx % O;
    int r  = idx / O;
    int o1 = r % O;  r /= O;
    int o0 = r % O;
    int b  = r / O;
    int inbase = ((b * NZ + B0 * o0) * O + o1) * O + o2;
    const int tapstride = TS * O * O;
    float acc[5];
#pragma unroll
    for (int f = 0; f < 5; f++) {
        const float* p = g_bufB + OFF + f * FS + inbase;
        float a = 0.f;
#pragma unroll
        for (int t = 0; t < K; t++) a += p[t * tapstride];
        acc[f] = a;
    }
    return lncc_eval(acc[0], acc[1], acc[2], acc[3], acc[4], numel);
}

// float4 helpers for the vectorized sc0 strips
__device__ __forceinline__ void add4(float4& a, const float4 b) {
    a.x += b.x; a.y += b.y; a.z += b.z; a.w += b.w;
}
__device__ __forceinline__ void sub4(float4& a, const float4 b) {
    a.x -= b.x; a.y -= b.y; a.z -= b.z; a.w -= b.w;
}

// sc0 strips, vectorized: thread = (b, strip(3 o0), o1, group of 4 o2).
// Planes are 16B-aligned thanks to O0W=72.
__device__ __forceinline__ float pass34_strip0_vec(int blk) {
    int idx = blk * 256 + threadIdx.x;
    if (idx >= NT0V) return 0.f;
    int g  = idx % NG0;
    int r  = idx / NG0;
    int o1 = r % O0;  r /= O0;
    int strip = r % NSTRIP0;
    int b     = r / NSTRIP0;
    int o2 = g * 4;
    int nv = (o2 + 4 <= O0) ? 4 : (O0 - o2);         // 4 or 3
    int o0s = strip * STRIP0;
    int nw  = (o0s + STRIP0 <= O0) ? STRIP0 : (O0 - o0s);  // 3 or 2
    const int PS = O0 * O0W;
    const float* p0 = g_bufB + OFF0 + (size_t)((b * NZ0) * O0 + o1) * O0W + o2;

    float4 a[5];
#pragma unroll
    for (int f = 0; f < 5; f++) a[f] = make_float4(0.f, 0.f, 0.f, 0.f);
#pragma unroll
    for (int j = 0; j < 9; j++) {
        const float* pp = p0 + (size_t)(o0s + j) * PS;
#pragma unroll
        for (int f = 0; f < 5; f++) add4(a[f], *(const float4*)(pp + f * FS0P));
    }
    float vsum = 0.f;
#pragma unroll
    for (int s = 0; s < STRIP0; s++) {
        if (s < nw) {
            const float* pl = p0 + (size_t)(o0s + 9 + s) * PS;
#pragma unroll
            for (int f = 0; f < 5; f++) add4(a[f], *(const float4*)(pl + f * FS0P));
            vsum += lncc_eval(a[0].x, a[1].x, a[2].x, a[3].x, a[4].x, 1000.f);
            vsum += lncc_eval(a[0].y, a[1].y, a[2].y, a[3].y, a[4].y, 1000.f);
            vsum += lncc_eval(a[0].z, a[1].z, a[2].z, a[3].z, a[4].z, 1000.f);
            if (nv == 4)
                vsum += lncc_eval(a[0].w, a[1].w, a[2].w, a[3].w, a[4].w, 1000.f);
            const float* pt = p0 + (size_t)(o0s + s) * PS;
#pragma unroll
            for (int f = 0; f < 5; f++) sub4(a[f], *(const float4*)(pt + f * FS0P));
        }
    }
    return vsum;
}

__global__ __launch_bounds__(256) void pass34_all(float* __restrict__ out) {
    int bb = blockIdx.x;
    float v;
    int pslot;
    if (bb < NBLK0V) {
        v = pass34_strip0_vec(bb);
        pslot = PB0 + bb;
    } else if (bb < NBLK0V + NBLK1) {
        v = pass34_gather<20, O1, NZ1c, 5, 2, OFF1, FS1, N3_1>(bb - NBLK0V);
        pslot = PB1 + (bb - NBLK0V);
    } else {
        v = pass34_gather<40, O2, NZ2, 5, 1, OFF2, FS2, N3_2>(bb - NBLK0V - NBLK1);
        pslot = PB2 + (bb - NBLK0V - NBLK1);
    }

    __shared__ float wsum[8];
    int lane = threadIdx.x & 31;
    int wid  = threadIdx.x >> 5;
#pragma unroll
    for (int o = 16; o > 0; o >>= 1) v += __shfl_down_sync(0xffffffffu, v, o);
    if (lane == 0) wsum[wid] = v;
    __syncthreads();
    if (wid == 0) {
        v = (lane < 8) ? wsum[lane] : 0.f;
#pragma unroll
        for (int o = 4; o > 0; o >>= 1) v += __shfl_down_sync(0xffffffffu, v, o);
        if (lane == 0) g_partials[pslot] = v;
    }

    __shared__ bool isLast;
    __threadfence();
    if (threadIdx.x == 0) {
        unsigned int old = atomicAdd(&g_count, 1u);
        isLast = (old == TOTBLK - 1);
    }
    __syncthreads();
    if (!isLast) return;
    __threadfence();

    __shared__ float sh[256];
    const int   pbase[3] = {PB0, PB1, PB2};
    const int   nblk[3]  = {NBLK0V, NBLK1, NBLK2};
    const float ninv[3]  = {1.0f / N3_0, 1.0f / N3_1, 1.0f / N3_2};
    const float wsc[3]   = {0.1f, 0.3f, 0.6f};
    float total = 0.f;
    for (int sc = 0; sc < 3; sc++) {
        float a = 0.f;
        for (int i = threadIdx.x; i < nblk[sc]; i += 256) a += g_partials[pbase[sc] + i];
        sh[threadIdx.x] = a;
        __syncthreads();
#pragma unroll
        for (int st = 128; st > 0; st >>= 1) {
            if (threadIdx.x < st) sh[threadIdx.x] += sh[threadIdx.x + st];
            __syncthreads();
        }
        if (threadIdx.x == 0) total += (1.0f - sh[0] * ninv[sc]) * wsc[sc];
        __syncthreads();
    }
    if (threadIdx.x == 0) {
        out[0] = total;
        g_count = 0;
    }
}

extern "C" void kernel_launch(void* const* d_in, const int* in_sizes, int n_in,
                              void* d_out, int out_size) {
    const float* x = (const float*)d_in[0];
    const float* y = (const float*)d_in[1];
    float* out = (float*)d_out;

    cudaFuncSetAttribute(fused_all,
                         cudaFuncAttributeMaxDynamicSharedMemorySize, SMEM_ALL);

    fused_all<<<GALL, 512, SMEM_ALL>>>(x, y);
    pass34_all<<<TOTBLK, 256>>>(out);
}